// round 13
// baseline (speedup 1.0000x reference)
#include <cuda_runtime.h>
#include <cuda_fp16.h>
#include <math.h>
#include <stdint.h>

#define BB   32
#define SS   4096
#define HID  512
#define MEMD 512
#define ATT  512

// ------------------------------- scratch -----------------------------------
__device__ float g_part[8 * BB * SS];   // score partials [n0t*2+warpN][row]
__device__ float g_h[BB * ATT];
// W_m permuted into per-thread fp16 fragment order for m16n8k16, BN=128 tiles.
// uint (half2) layout: [n0t(4)][stage(16)][i8(8)][chunk(64)][e(4)]  (131072 u32)
//   i8 = kk*4 + kb*2 + jq ; j = jq*4 + e ; chunk = warpN*32 + lane
//   half2 = { W[k][n], W[k+1][n] },  k = s*32 + kk*16 + kb*8 + 2*tg
//   n = n0t*128 + warpN*64 + j*8 + g
#define WP16_N (4 * 16 * 8 * 64 * 4)    // 131072
__device__ unsigned int g_Wp16[WP16_N];

// ------------------------------- helpers -----------------------------------
__device__ __forceinline__ uint32_t smem_u32(const void* p) {
    return (uint32_t)__cvta_generic_to_shared(p);
}
__device__ __forceinline__ void cp16(uint32_t dst, const void* src) {
    asm volatile("cp.async.cg.shared.global [%0], [%1], 16;\n" :: "r"(dst), "l"(src));
}
__device__ __forceinline__ void cp_commit() { asm volatile("cp.async.commit_group;\n" ::: "memory"); }
template <int N>
__device__ __forceinline__ void cp_wait() {
    asm volatile("cp.async.wait_group %0;\n" :: "n"(N) : "memory");
}
// pack float2 {x=k_even, y=k_odd} -> f16x2 reg (lo = x)
__device__ __forceinline__ uint32_t pack_f16x2(float2 p) {
    uint32_t d;
    asm("cvt.rn.f16x2.f32 %0, %1, %2;" : "=r"(d) : "f"(p.y), "f"(p.x));
    return d;
}
__device__ __forceinline__ void mma_f16(float* d, uint32_t a0, uint32_t a1,
                                        uint32_t a2, uint32_t a3,
                                        uint32_t b0, uint32_t b1) {
    asm volatile(
        "mma.sync.aligned.m16n8k16.row.col.f32.f16.f16.f32 "
        "{%0,%1,%2,%3}, {%4,%5,%6,%7}, {%8,%9}, {%0,%1,%2,%3};"
        : "+f"(d[0]), "+f"(d[1]), "+f"(d[2]), "+f"(d[3])
        : "r"(a0), "r"(a1), "r"(a2), "r"(a3), "r"(b0), "r"(b1));
}
__device__ __forceinline__ float tanh_fast(float x) {
    float y; asm("tanh.approx.f32 %0, %1;" : "=f"(y) : "f"(x)); return y;
}

// ---------------------------------------------------------------------------
// Prologue (one kernel): blocks [0,512) permute W_m -> g_Wp16 (131072 elems);
// blocks [512,544) compute h[b][:] and zero the context output.
// block = 256 threads. grid = 544.
// ---------------------------------------------------------------------------
__global__ void prologue_kernel(const float* __restrict__ Wm,
                                const float* __restrict__ hidden,
                                const float* __restrict__ W_h,
                                float* __restrict__ out_ctx) {
    if (blockIdx.x < 512) {
        int o = blockIdx.x * 256 + threadIdx.x;   // 0 .. 131071 == WP16_N-1
        int e     = o & 3;
        int chunk = (o >> 2) & 63;
        int i8    = (o >> 8) & 7;
        int s     = (o >> 11) & 15;
        int n0t   = o >> 15;                      // 0..3
        int kk = i8 >> 2, kb = (i8 >> 1) & 1, jq = i8 & 1;
        int j = jq * 4 + e;
        int lane = chunk & 31, warpN = chunk >> 5;
        int g = lane >> 2, tg = lane & 3;
        int k = s * 32 + kk * 16 + kb * 8 + 2 * tg;
        int n = n0t * 128 + warpN * 64 + j * 8 + g;
        __half2 h = __floats2half2_rn(Wm[k * ATT + n], Wm[(k + 1) * ATT + n]);
        g_Wp16[o] = *reinterpret_cast<unsigned int*>(&h);
    } else {
        __shared__ float sh[HID];
        const int b = blockIdx.x - 512;           // 0..31
        const int t = threadIdx.x;                // 0..255
        sh[t]       = hidden[b * HID + t];
        sh[t + 256] = hidden[b * HID + t + 256];
        __syncthreads();
#pragma unroll
        for (int rep = 0; rep < 2; rep++) {
            const int a = t + rep * 256;
            float acc = 0.0f;
#pragma unroll 8
            for (int d = 0; d < HID; d++) acc += sh[d] * W_h[d * ATT + a];
            g_h[b * ATT + a] = acc;
            out_ctx[b * MEMD + a] = 0.0f;
        }
    }
}

// ---------------------------------------------------------------------------
// Score GEMM (fp16 m16n8k16, fp32 accumulate) + tanh/v epilogue.
// CTA tile 128(M) x 128(N), 8 warps (4M x 2N), warp tile 32x64, 256 threads.
// 2 CTAs/SM. A fp32 in smem (AST=40, conflict-free); B pre-permuted fp16.
// 3-stage cp.async pipeline (R9 mainloop, unchanged).
// Epilogue writes per-(n0t,warpN) partials to g_part (no atomics).
// grid = (4 n-tiles, 1024 m-tiles).
// ---------------------------------------------------------------------------
#define BM 128
#define BN 128
#define BK 32
#define AST 40                        // conflict-free for fragment LDS.64
#define A_TILE (BM * AST)             // 5120 floats / stage (20KB)
#define B_TILE_U (8 * 64 * 4)         // 2048 uints / stage (8KB)
#define NSTAGE (MEMD / BK)            // 16
#define AUX_OFF (3 * A_TILE + 3 * B_TILE_U)
#define SMEM_DYN ((AUX_OFF + 3 * 512) * 4)

__global__ void __launch_bounds__(256, 2) score_mma(
    const float* __restrict__ Amem,
    const float* __restrict__ coverage,
    const float* __restrict__ Wc,
    const float* __restrict__ vvec) {

    extern __shared__ float dsm[];
    float* As_all = dsm;                                      // 3 * A_TILE fp32
    unsigned int* Bs_all = (unsigned int*)(dsm + 3 * A_TILE); // 3 * B_TILE_U
    float* sh_h   = dsm + AUX_OFF;                            // 512 (absolute)
    float* sh_wc  = sh_h + 512;
    float* sh_v   = sh_wc + 512;

    const int tid   = threadIdx.x;
    const int lane  = tid & 31;
    const int wid   = tid >> 5;     // 0..7
    const int warpN = wid & 1;      // 0..1
    const int warpM = wid >> 1;     // 0..3
    const int g     = lane >> 2;    // 0..7
    const int tg    = lane & 3;     // 0..3
    const int chunkB = warpN * 32 + lane;

    const int  n0t  = blockIdx.x;
    const int  n0   = n0t * BN;
    const long row0 = (long)blockIdx.y * BM;
    const int  b    = (int)(row0 >> 12);

    for (int i = tid; i < 512; i += 256) {
        sh_h[i]  = g_h[b * 512 + i];
        sh_wc[i] = Wc[i];
        sh_v[i]  = vvec[i];
    }

    float acc[2][8][4];
#pragma unroll
    for (int i = 0; i < 2; i++)
#pragma unroll
        for (int j = 0; j < 8; j++)
#pragma unroll
            for (int c = 0; c < 4; c++) acc[i][j][c] = 0.0f;

    const unsigned int* BsrcBase = g_Wp16 + (long)n0t * 16 * B_TILE_U;

    auto load_stage = [&](int s) {
        const int buf = s % 3;
        uint32_t Abu = smem_u32(As_all + buf * A_TILE);
        uint32_t Bbu = smem_u32(Bs_all + buf * B_TILE_U);
        const int k0 = s * BK;
        // A: 128 rows x 8 float4 = 1024 cp16 over 256 threads -> 4 each
#pragma unroll
        for (int j = 0; j < 4; j++) {
            int c = tid + 256 * j;
            int r = c >> 3, c4 = c & 7;
            cp16(Abu + (r * AST + c4 * 4) * 4, Amem + (row0 + r) * 512 + k0 + c4 * 4);
        }
        // B: 512 uint4 -> 2 each (coalesced)
        const unsigned int* Bsrc = BsrcBase + (long)s * B_TILE_U;
#pragma unroll
        for (int j = 0; j < 2; j++) {
            int u4 = tid + 256 * j;
            cp16(Bbu + u4 * 16, Bsrc + u4 * 4);
        }
        cp_commit();
    };

    load_stage(0);
    load_stage(1);

    for (int s = 0; s < NSTAGE; s++) {
        if (s < NSTAGE - 1) cp_wait<1>(); else cp_wait<0>();
        __syncthreads();
        if (s + 2 < NSTAGE) load_stage(s + 2);

        const int buf = s % 3;
        const float* Ab = As_all + buf * A_TILE;
        const uint4* B4 = (const uint4*)(Bs_all + buf * B_TILE_U);

#pragma unroll
        for (int kk = 0; kk < 2; kk++) {
            // B fragments: 4x LDS.128 (conflict-free)
            uint4 q0 = B4[(kk * 4 + 0) * 64 + chunkB];  // b0, j0-3
            uint4 q1 = B4[(kk * 4 + 1) * 64 + chunkB];  // b0, j4-7
            uint4 q2 = B4[(kk * 4 + 2) * 64 + chunkB];  // b1, j0-3
            uint4 q3 = B4[(kk * 4 + 3) * 64 + chunkB];  // b1, j4-7
            uint32_t b0[8] = {q0.x, q0.y, q0.z, q0.w, q1.x, q1.y, q1.z, q1.w};
            uint32_t b1[8] = {q2.x, q2.y, q2.z, q2.w, q3.x, q3.y, q3.z, q3.w};

#pragma unroll
            for (int i = 0; i < 2; i++) {
                // A fragments: 4x LDS.64, conflict-free with AST=40
                const int r = warpM * 32 + i * 16 + g;
                const int kbase = kk * 16 + 2 * tg;
                float2 p0 = *(const float2*)(Ab + r * AST + kbase);
                float2 p1 = *(const float2*)(Ab + (r + 8) * AST + kbase);
                float2 p2 = *(const float2*)(Ab + r * AST + kbase + 8);
                float2 p3 = *(const float2*)(Ab + (r + 8) * AST + kbase + 8);
                uint32_t a0 = pack_f16x2(p0);
                uint32_t a1 = pack_f16x2(p1);
                uint32_t a2 = pack_f16x2(p2);
                uint32_t a3 = pack_f16x2(p3);
#pragma unroll
                for (int j = 0; j < 8; j++)
                    mma_f16(acc[i][j], a0, a1, a2, a3, b0[j], b1[j]);
            }
        }
    }

    // ---- epilogue: tanh + v-dot partial over this CTA's 128 n-cols ----
    float* pslot = g_part + (long)(n0t * 2 + warpN) * (BB * SS);
#pragma unroll
    for (int i = 0; i < 2; i++) {
        const int r_lo = warpM * 32 + i * 16 + g;
        const int r_hi = r_lo + 8;
        const float cov_lo = coverage[row0 + r_lo];
        const float cov_hi = coverage[row0 + r_hi];
        float p_lo = 0.0f, p_hi = 0.0f;
#pragma unroll
        for (int j = 0; j < 8; j++) {
            const int nb = n0 + warpN * 64 + j * 8 + tg * 2;  // absolute col
            const float h0 = sh_h[nb + 0], h1 = sh_h[nb + 1];
            const float w0 = sh_wc[nb + 0], w1 = sh_wc[nb + 1];
            const float v0 = sh_v[nb + 0], v1 = sh_v[nb + 1];
            p_lo += tanh_fast(acc[i][j][0] + h0 + cov_lo * w0) * v0;
            p_lo += tanh_fast(acc[i][j][1] + h1 + cov_lo * w1) * v1;
            p_hi += tanh_fast(acc[i][j][2] + h0 + cov_hi * w0) * v0;
            p_hi += tanh_fast(acc[i][j][3] + h1 + cov_hi * w1) * v1;
        }
        p_lo += __shfl_xor_sync(0xffffffffu, p_lo, 1);
        p_lo += __shfl_xor_sync(0xffffffffu, p_lo, 2);
        p_hi += __shfl_xor_sync(0xffffffffu, p_hi, 1);
        p_hi += __shfl_xor_sync(0xffffffffu, p_hi, 2);
        if (tg == 0) {
            pslot[row0 + r_lo] = p_lo;
            pslot[row0 + r_hi] = p_hi;
        }
    }
}

// ---------------------------------------------------------------------------
// Softmax over S per batch (with pad mask), summing the 8 score partials.
// grid=B, block=1024.
// ---------------------------------------------------------------------------
__global__ void softmax_kernel(const unsigned char* __restrict__ pad,
                               float* __restrict__ attn) {
    __shared__ float red[1024];
    const int b = blockIdx.x;
    const int tid = threadIdx.x;

    float mx = -INFINITY;
    float sc_loc[SS / 1024];
#pragma unroll
    for (int it = 0; it < SS / 1024; it++) {
        int s = tid + it * 1024;
        long row = (long)b * SS + s;
        float sc = 0.0f;
#pragma unroll
        for (int p = 0; p < 8; p++) sc += g_part[(long)p * (BB * SS) + row];
        sc = pad[row] ? -INFINITY : sc;
        sc_loc[it] = sc;
        mx = fmaxf(mx, sc);
    }
    red[tid] = mx;
    __syncthreads();
    for (int off = 512; off > 0; off >>= 1) {
        if (tid < off) red[tid] = fmaxf(red[tid], red[tid + off]);
        __syncthreads();
    }
    mx = red[0];
    __syncthreads();

    float sum = 0.0f;
#pragma unroll
    for (int it = 0; it < SS / 1024; it++) {
        int s = tid + it * 1024;
        float e = expf(sc_loc[it] - mx);
        attn[b * SS + s] = e;
        sum += e;
    }
    red[tid] = sum;
    __syncthreads();
    for (int off = 512; off > 0; off >>= 1) {
        if (tid < off) red[tid] += red[tid + off];
        __syncthreads();
    }
    float inv = 1.0f / red[0];
#pragma unroll
    for (int it = 0; it < SS / 1024; it++) {
        int s = tid + it * 1024;
        attn[b * SS + s] *= inv;
    }
}

// ---------------------------------------------------------------------------
// context[b][d] = sum_s attn[b][s] * memory[b][s][d]. grid=(B,32), block=512.
// ---------------------------------------------------------------------------
__global__ void context_kernel(const float* __restrict__ memory,
                               const float* __restrict__ attn,
                               float* __restrict__ ctx) {
    __shared__ float w[128];
    const int b = blockIdx.x;
    const int s0 = blockIdx.y * 128;
    const int d = threadIdx.x;

    if (d < 128) w[d] = attn[b * SS + s0 + d];
    __syncthreads();

    float acc = 0.0f;
    const float* mbase = memory + ((long)b * SS + s0) * MEMD + d;
#pragma unroll 4
    for (int s = 0; s < 128; s++) acc += w[s] * mbase[(long)s * MEMD];
    atomicAdd(&ctx[b * MEMD + d], acc);
}

// ---------------------------------------------------------------------------
// Launch.  Inputs (metadata order):
//   0 hidden | 1 memory | 2 mem_pad | 3 coverage | 4 W_h | 5 W_m | 6 W_c | 7 v
// Output: [context (B*MEM) | attn (B*S)] f32
// ---------------------------------------------------------------------------
extern "C" void kernel_launch(void* const* d_in, const int* in_sizes, int n_in,
                              void* d_out, int out_size) {
    const float* hidden   = (const float*)d_in[0];
    const float* memory   = (const float*)d_in[1];
    const unsigned char* mem_pad = (const unsigned char*)d_in[2];
    const float* coverage = (const float*)d_in[3];
    const float* W_h      = (const float*)d_in[4];
    const float* W_m      = (const float*)d_in[5];
    const float* W_c      = (const float*)d_in[6];
    const float* v        = (const float*)d_in[7];

    float* out = (float*)d_out;
    float* out_ctx  = out;
    float* out_attn = out + BB * MEMD;

    cudaFuncSetAttribute(score_mma, cudaFuncAttributeMaxDynamicSharedMemorySize,
                         SMEM_DYN);

    prologue_kernel<<<544, 256>>>(W_m, hidden, W_h, out_ctx);
    {
        dim3 grid(ATT / BN, BB * SS / BM);
        score_mma<<<grid, 256, SMEM_DYN>>>(memory, coverage, W_c, v);
    }
    softmax_kernel<<<BB, 1024>>>(mem_pad, out_attn);
    {
        dim3 grid(BB, SS / 128);
        context_kernel<<<grid, 512>>>(memory, out_attn, out_ctx);
    }
}

// round 14
// speedup vs baseline: 1.0160x; 1.0160x over previous
#include <cuda_runtime.h>
#include <cuda_fp16.h>
#include <math.h>
#include <stdint.h>

#define BB   32
#define SS   4096
#define HID  512
#define MEMD 512
#define ATT  512

// ------------------------------- scratch -----------------------------------
__device__ float g_scores[BB * SS];
__device__ float g_h[BB * ATT];
// W_m permuted into per-thread fp16 fragment order for m16n8k16, BN=128 tiles.
// uint (half2) layout: [n0t(4)][stage(16)][i8(8)][chunk(64)][e(4)]  (131072 u32)
#define WP16_N (4 * 16 * 8 * 64 * 4)    // 131072
__device__ unsigned int g_Wp16[WP16_N];

// ------------------------------- helpers -----------------------------------
__device__ __forceinline__ uint32_t smem_u32(const void* p) {
    return (uint32_t)__cvta_generic_to_shared(p);
}
__device__ __forceinline__ void cp16(uint32_t dst, const void* src) {
    asm volatile("cp.async.cg.shared.global [%0], [%1], 16;\n" :: "r"(dst), "l"(src));
}
__device__ __forceinline__ void cp_commit() { asm volatile("cp.async.commit_group;\n" ::: "memory"); }
template <int N>
__device__ __forceinline__ void cp_wait() {
    asm volatile("cp.async.wait_group %0;\n" :: "n"(N) : "memory");
}
// pack float2 {x=k_even, y=k_odd} -> f16x2 reg (lo = x)
__device__ __forceinline__ uint32_t pack_f16x2(float2 p) {
    uint32_t d;
    asm("cvt.rn.f16x2.f32 %0, %1, %2;" : "=r"(d) : "f"(p.y), "f"(p.x));
    return d;
}
__device__ __forceinline__ void mma_f16(float* d, uint32_t a0, uint32_t a1,
                                        uint32_t a2, uint32_t a3,
                                        uint32_t b0, uint32_t b1) {
    asm volatile(
        "mma.sync.aligned.m16n8k16.row.col.f32.f16.f16.f32 "
        "{%0,%1,%2,%3}, {%4,%5,%6,%7}, {%8,%9}, {%0,%1,%2,%3};"
        : "+f"(d[0]), "+f"(d[1]), "+f"(d[2]), "+f"(d[3])
        : "r"(a0), "r"(a1), "r"(a2), "r"(a3), "r"(b0), "r"(b1));
}
__device__ __forceinline__ float tanh_fast(float x) {
    float y; asm("tanh.approx.f32 %0, %1;" : "=f"(y) : "f"(x)); return y;
}

// ---------------------------------------------------------------------------
// Prologue (one kernel), grid = 672, block = 256:
//   blocks [0,512)   : permute W_m -> g_Wp16 (131072 half2)
//   blocks [512,544) : h[b][:] = hidden[b] @ W_h ; zero context output
//   blocks [544,672) : zero g_scores (float4)
// ---------------------------------------------------------------------------
__global__ void prologue_kernel(const float* __restrict__ Wm,
                                const float* __restrict__ hidden,
                                const float* __restrict__ W_h,
                                float* __restrict__ out_ctx) {
    if (blockIdx.x < 512) {
        int o = blockIdx.x * 256 + threadIdx.x;   // 0 .. 131071
        int e     = o & 3;
        int chunk = (o >> 2) & 63;
        int i8    = (o >> 8) & 7;
        int s     = (o >> 11) & 15;
        int n0t   = o >> 15;                      // 0..3
        int kk = i8 >> 2, kb = (i8 >> 1) & 1, jq = i8 & 1;
        int j = jq * 4 + e;
        int lane = chunk & 31, warpN = chunk >> 5;
        int g = lane >> 2, tg = lane & 3;
        int k = s * 32 + kk * 16 + kb * 8 + 2 * tg;
        int n = n0t * 128 + warpN * 64 + j * 8 + g;
        __half2 h = __floats2half2_rn(Wm[k * ATT + n], Wm[(k + 1) * ATT + n]);
        g_Wp16[o] = *reinterpret_cast<unsigned int*>(&h);
    } else if (blockIdx.x < 544) {
        __shared__ float sh[HID];
        const int b = blockIdx.x - 512;           // 0..31
        const int t = threadIdx.x;                // 0..255
        sh[t]       = hidden[b * HID + t];
        sh[t + 256] = hidden[b * HID + t + 256];
        __syncthreads();
#pragma unroll
        for (int rep = 0; rep < 2; rep++) {
            const int a = t + rep * 256;
            float acc = 0.0f;
#pragma unroll 8
            for (int d = 0; d < HID; d++) acc += sh[d] * W_h[d * ATT + a];
            g_h[b * ATT + a] = acc;
            out_ctx[b * MEMD + a] = 0.0f;
        }
    } else {
        int i = (blockIdx.x - 544) * 256 + threadIdx.x;   // 0..32767 float4s
        reinterpret_cast<float4*>(g_scores)[i] = make_float4(0.f, 0.f, 0.f, 0.f);
    }
}

// ---------------------------------------------------------------------------
// Score GEMM (fp16 m16n8k16, fp32 accumulate) + tanh/v epilogue.
// CTA tile 128(M) x 128(N), 8 warps (4M x 2N), warp tile 32x64, 256 threads.
// 2 CTAs/SM. A fp32 in smem (AST=40, conflict-free); B pre-permuted fp16.
// 3-stage cp.async pipeline. grid = (4 n-tiles, 1024 m-tiles).
// *** R9 version, byte-for-byte: epilogue uses atomicAdd into g_scores. ***
// ---------------------------------------------------------------------------
#define BM 128
#define BN 128
#define BK 32
#define AST 40                        // conflict-free for fragment LDS.64
#define A_TILE (BM * AST)             // 5120 floats / stage (20KB)
#define B_TILE_U (8 * 64 * 4)         // 2048 uints / stage (8KB)
#define NSTAGE (MEMD / BK)            // 16
#define AUX_OFF (3 * A_TILE + 3 * B_TILE_U)
#define SMEM_DYN ((AUX_OFF + 3 * 512) * 4)

__global__ void __launch_bounds__(256, 2) score_mma(
    const float* __restrict__ Amem,
    const float* __restrict__ coverage,
    const float* __restrict__ Wc,
    const float* __restrict__ vvec) {

    extern __shared__ float dsm[];
    float* As_all = dsm;                                      // 3 * A_TILE fp32
    unsigned int* Bs_all = (unsigned int*)(dsm + 3 * A_TILE); // 3 * B_TILE_U
    float* sh_h   = dsm + AUX_OFF;                            // 512 (absolute)
    float* sh_wc  = sh_h + 512;
    float* sh_v   = sh_wc + 512;

    const int tid   = threadIdx.x;
    const int lane  = tid & 31;
    const int wid   = tid >> 5;     // 0..7
    const int warpN = wid & 1;      // 0..1
    const int warpM = wid >> 1;     // 0..3
    const int g     = lane >> 2;    // 0..7
    const int tg    = lane & 3;     // 0..3
    const int chunkB = warpN * 32 + lane;

    const int  n0t  = blockIdx.x;
    const int  n0   = n0t * BN;
    const long row0 = (long)blockIdx.y * BM;
    const int  b    = (int)(row0 >> 12);

    for (int i = tid; i < 512; i += 256) {
        sh_h[i]  = g_h[b * 512 + i];
        sh_wc[i] = Wc[i];
        sh_v[i]  = vvec[i];
    }

    float acc[2][8][4];
#pragma unroll
    for (int i = 0; i < 2; i++)
#pragma unroll
        for (int j = 0; j < 8; j++)
#pragma unroll
            for (int c = 0; c < 4; c++) acc[i][j][c] = 0.0f;

    const unsigned int* BsrcBase = g_Wp16 + (long)n0t * 16 * B_TILE_U;

    auto load_stage = [&](int s) {
        const int buf = s % 3;
        uint32_t Abu = smem_u32(As_all + buf * A_TILE);
        uint32_t Bbu = smem_u32(Bs_all + buf * B_TILE_U);
        const int k0 = s * BK;
        // A: 128 rows x 8 float4 = 1024 cp16 over 256 threads -> 4 each
#pragma unroll
        for (int j = 0; j < 4; j++) {
            int c = tid + 256 * j;
            int r = c >> 3, c4 = c & 7;
            cp16(Abu + (r * AST + c4 * 4) * 4, Amem + (row0 + r) * 512 + k0 + c4 * 4);
        }
        // B: 512 uint4 -> 2 each (coalesced)
        const unsigned int* Bsrc = BsrcBase + (long)s * B_TILE_U;
#pragma unroll
        for (int j = 0; j < 2; j++) {
            int u4 = tid + 256 * j;
            cp16(Bbu + u4 * 16, Bsrc + u4 * 4);
        }
        cp_commit();
    };

    load_stage(0);
    load_stage(1);

    for (int s = 0; s < NSTAGE; s++) {
        if (s < NSTAGE - 1) cp_wait<1>(); else cp_wait<0>();
        __syncthreads();
        if (s + 2 < NSTAGE) load_stage(s + 2);

        const int buf = s % 3;
        const float* Ab = As_all + buf * A_TILE;
        const uint4* B4 = (const uint4*)(Bs_all + buf * B_TILE_U);

#pragma unroll
        for (int kk = 0; kk < 2; kk++) {
            // B fragments: 4x LDS.128 (conflict-free)
            uint4 q0 = B4[(kk * 4 + 0) * 64 + chunkB];  // b0, j0-3
            uint4 q1 = B4[(kk * 4 + 1) * 64 + chunkB];  // b0, j4-7
            uint4 q2 = B4[(kk * 4 + 2) * 64 + chunkB];  // b1, j0-3
            uint4 q3 = B4[(kk * 4 + 3) * 64 + chunkB];  // b1, j4-7
            uint32_t b0[8] = {q0.x, q0.y, q0.z, q0.w, q1.x, q1.y, q1.z, q1.w};
            uint32_t b1[8] = {q2.x, q2.y, q2.z, q2.w, q3.x, q3.y, q3.z, q3.w};

#pragma unroll
            for (int i = 0; i < 2; i++) {
                // A fragments: 4x LDS.64, conflict-free with AST=40
                const int r = warpM * 32 + i * 16 + g;
                const int kbase = kk * 16 + 2 * tg;
                float2 p0 = *(const float2*)(Ab + r * AST + kbase);
                float2 p1 = *(const float2*)(Ab + (r + 8) * AST + kbase);
                float2 p2 = *(const float2*)(Ab + r * AST + kbase + 8);
                float2 p3 = *(const float2*)(Ab + (r + 8) * AST + kbase + 8);
                uint32_t a0 = pack_f16x2(p0);
                uint32_t a1 = pack_f16x2(p1);
                uint32_t a2 = pack_f16x2(p2);
                uint32_t a3 = pack_f16x2(p3);
#pragma unroll
                for (int j = 0; j < 8; j++)
                    mma_f16(acc[i][j], a0, a1, a2, a3, b0[j], b1[j]);
            }
        }
    }

    // ---- epilogue: tanh + v-dot partial over this CTA's 128 n-cols ----
#pragma unroll
    for (int i = 0; i < 2; i++) {
        const int r_lo = warpM * 32 + i * 16 + g;
        const int r_hi = r_lo + 8;
        const float cov_lo = coverage[row0 + r_lo];
        const float cov_hi = coverage[row0 + r_hi];
        float p_lo = 0.0f, p_hi = 0.0f;
#pragma unroll
        for (int j = 0; j < 8; j++) {
            const int nb = n0 + warpN * 64 + j * 8 + tg * 2;  // absolute col
            const float h0 = sh_h[nb + 0], h1 = sh_h[nb + 1];
            const float w0 = sh_wc[nb + 0], w1 = sh_wc[nb + 1];
            const float v0 = sh_v[nb + 0], v1 = sh_v[nb + 1];
            p_lo += tanh_fast(acc[i][j][0] + h0 + cov_lo * w0) * v0;
            p_lo += tanh_fast(acc[i][j][1] + h1 + cov_lo * w1) * v1;
            p_hi += tanh_fast(acc[i][j][2] + h0 + cov_hi * w0) * v0;
            p_hi += tanh_fast(acc[i][j][3] + h1 + cov_hi * w1) * v1;
        }
        p_lo += __shfl_xor_sync(0xffffffffu, p_lo, 1);
        p_lo += __shfl_xor_sync(0xffffffffu, p_lo, 2);
        p_hi += __shfl_xor_sync(0xffffffffu, p_hi, 1);
        p_hi += __shfl_xor_sync(0xffffffffu, p_hi, 2);
        if (tg == 0) {
            atomicAdd(&g_scores[row0 + r_lo], p_lo);
            atomicAdd(&g_scores[row0 + r_hi], p_hi);
        }
    }
}

// ---------------------------------------------------------------------------
// Softmax over S per batch (with pad mask). grid=B, block=1024.
// ---------------------------------------------------------------------------
__global__ void softmax_kernel(const unsigned char* __restrict__ pad,
                               float* __restrict__ attn) {
    __shared__ float red[1024];
    const int b = blockIdx.x;
    const int tid = threadIdx.x;

    float mx = -INFINITY;
    for (int s = tid; s < SS; s += 1024) {
        float sc = pad[b * SS + s] ? -INFINITY : g_scores[b * SS + s];
        mx = fmaxf(mx, sc);
    }
    red[tid] = mx;
    __syncthreads();
    for (int off = 512; off > 0; off >>= 1) {
        if (tid < off) red[tid] = fmaxf(red[tid], red[tid + off]);
        __syncthreads();
    }
    mx = red[0];
    __syncthreads();

    float sum = 0.0f;
    for (int s = tid; s < SS; s += 1024) {
        float sc = pad[b * SS + s] ? -INFINITY : g_scores[b * SS + s];
        float e = expf(sc - mx);
        attn[b * SS + s] = e;
        sum += e;
    }
    red[tid] = sum;
    __syncthreads();
    for (int off = 512; off > 0; off >>= 1) {
        if (tid < off) red[tid] += red[tid + off];
        __syncthreads();
    }
    float inv = 1.0f / red[0];
    for (int s = tid; s < SS; s += 1024) attn[b * SS + s] *= inv;
}

// ---------------------------------------------------------------------------
// context[b][d] = sum_s attn[b][s] * memory[b][s][d].
// grid=(B,32), block=128. Each thread owns 4 consecutive d (float4 loads).
// ---------------------------------------------------------------------------
__global__ void context_kernel(const float* __restrict__ memory,
                               const float* __restrict__ attn,
                               float* __restrict__ ctx) {
    __shared__ float w[128];
    const int b = blockIdx.x;
    const int s0 = blockIdx.y * 128;
    const int t = threadIdx.x;          // 0..127
    const int d = t * 4;

    w[t] = attn[b * SS + s0 + t];
    __syncthreads();

    float4 acc = make_float4(0.f, 0.f, 0.f, 0.f);
    const float* mbase = memory + ((long)b * SS + s0) * MEMD + d;
#pragma unroll 4
    for (int s = 0; s < 128; s++) {
        float4 m = *reinterpret_cast<const float4*>(mbase + (long)s * MEMD);
        float ws = w[s];
        acc.x += ws * m.x;
        acc.y += ws * m.y;
        acc.z += ws * m.z;
        acc.w += ws * m.w;
    }
    atomicAdd(&ctx[b * MEMD + d + 0], acc.x);
    atomicAdd(&ctx[b * MEMD + d + 1], acc.y);
    atomicAdd(&ctx[b * MEMD + d + 2], acc.z);
    atomicAdd(&ctx[b * MEMD + d + 3], acc.w);
}

// ---------------------------------------------------------------------------
// Launch.  Inputs (metadata order):
//   0 hidden | 1 memory | 2 mem_pad | 3 coverage | 4 W_h | 5 W_m | 6 W_c | 7 v
// Output: [context (B*MEM) | attn (B*S)] f32
// ---------------------------------------------------------------------------
extern "C" void kernel_launch(void* const* d_in, const int* in_sizes, int n_in,
                              void* d_out, int out_size) {
    const float* hidden   = (const float*)d_in[0];
    const float* memory   = (const float*)d_in[1];
    const unsigned char* mem_pad = (const unsigned char*)d_in[2];
    const float* coverage = (const float*)d_in[3];
    const float* W_h      = (const float*)d_in[4];
    const float* W_m      = (const float*)d_in[5];
    const float* W_c      = (const float*)d_in[6];
    const float* v        = (const float*)d_in[7];

    float* out = (float*)d_out;
    float* out_ctx  = out;
    float* out_attn = out + BB * MEMD;

    cudaFuncSetAttribute(score_mma, cudaFuncAttributeMaxDynamicSharedMemorySize,
                         SMEM_DYN);

    prologue_kernel<<<672, 256>>>(W_m, hidden, W_h, out_ctx);
    {
        dim3 grid(ATT / BN, BB * SS / BM);
        score_mma<<<grid, 256, SMEM_DYN>>>(memory, coverage, W_c, v);
    }
    softmax_kernel<<<BB, 1024>>>(mem_pad, out_attn);
    {
        dim3 grid(BB, SS / 128);
        context_kernel<<<grid, 128>>>(memory, out_attn, out_ctx);
    }
}

// round 15
// speedup vs baseline: 1.1214x; 1.1038x over previous
#include <cuda_runtime.h>
#include <cuda_fp16.h>
#include <math.h>
#include <stdint.h>

#define BB   32
#define SS   4096
#define HID  512
#define MEMD 512
#define ATT  512

// ------------------------------- scratch -----------------------------------
__device__ float g_scores[BB * SS];
__device__ float g_h[BB * ATT];
// W_m permuted into per-thread fp16 fragment order for m16n8k16, BN=128 tiles.
// uint (half2) layout: [n0t(4)][stage(16)][i8(8)][chunk(64)][e(4)]
//   i8 = kk*4 + kb*2 + jq ; j = jq*4 + e ; chunk = warpN*32 + lane
//   half2 = { W[k][n], W[k+1][n] },  k = s*32 + kk*16 + kb*8 + 2*tg
//   n = n0t*128 + warpN*64 + j*8 + g
__device__ unsigned int g_Wp16[4 * 16 * 8 * 64 * 4];

// ------------------------------- helpers -----------------------------------
__device__ __forceinline__ uint32_t smem_u32(const void* p) {
    return (uint32_t)__cvta_generic_to_shared(p);
}
__device__ __forceinline__ void cp16(uint32_t dst, const void* src) {
    asm volatile("cp.async.cg.shared.global [%0], [%1], 16;\n" :: "r"(dst), "l"(src));
}
__device__ __forceinline__ void cp_commit() { asm volatile("cp.async.commit_group;\n" ::: "memory"); }
template <int N>
__device__ __forceinline__ void cp_wait() {
    asm volatile("cp.async.wait_group %0;\n" :: "n"(N) : "memory");
}
// pack float2 {x=k_even, y=k_odd} -> f16x2 reg (lo = x)
__device__ __forceinline__ uint32_t pack_f16x2(float2 p) {
    uint32_t d;
    asm("cvt.rn.f16x2.f32 %0, %1, %2;" : "=r"(d) : "f"(p.y), "f"(p.x));
    return d;
}
__device__ __forceinline__ void mma_f16(float* d, uint32_t a0, uint32_t a1,
                                        uint32_t a2, uint32_t a3,
                                        uint32_t b0, uint32_t b1) {
    asm volatile(
        "mma.sync.aligned.m16n8k16.row.col.f32.f16.f16.f32 "
        "{%0,%1,%2,%3}, {%4,%5,%6,%7}, {%8,%9}, {%0,%1,%2,%3};"
        : "+f"(d[0]), "+f"(d[1]), "+f"(d[2]), "+f"(d[3])
        : "r"(a0), "r"(a1), "r"(a2), "r"(a3), "r"(b0), "r"(b1));
}
__device__ __forceinline__ float tanh_fast(float x) {
    float y; asm("tanh.approx.f32 %0, %1;" : "=f"(y) : "f"(x)); return y;
}

// ---------------------------------------------------------------------------
// zero: scores scratch + context output region
// ---------------------------------------------------------------------------
__global__ void zero_kernel(float* __restrict__ out_ctx) {
    int i = blockIdx.x * blockDim.x + threadIdx.x;
    if (i < BB * SS) g_scores[i] = 0.0f;
    if (i < BB * MEMD) out_ctx[i] = 0.0f;
}

// ---------------------------------------------------------------------------
// Build g_Wp16 (fp16 permuted fragment layout, BN=128). One thread per half2.
// ---------------------------------------------------------------------------
__global__ void permute_wm16(const float* __restrict__ Wm) {
    int o = blockIdx.x * blockDim.x + threadIdx.x;
    if (o >= 4 * 16 * 8 * 64 * 4) return;
    int e     = o & 3;
    int chunk = (o >> 2) & 63;
    int i8    = (o >> 8) & 7;
    int s     = (o >> 11) & 15;
    int n0t   = o >> 15;
    int kk = i8 >> 2, kb = (i8 >> 1) & 1, jq = i8 & 1;
    int j = jq * 4 + e;
    int lane = chunk & 31, warpN = chunk >> 5;
    int g = lane >> 2, tg = lane & 3;
    int k = s * 32 + kk * 16 + kb * 8 + 2 * tg;
    int n = n0t * 128 + warpN * 64 + j * 8 + g;
    __half2 h = __floats2half2_rn(Wm[k * ATT + n], Wm[(k + 1) * ATT + n]);
    g_Wp16[o] = *reinterpret_cast<unsigned int*>(&h);
}

// ---------------------------------------------------------------------------
// h[b][a] = hidden[b] . W_h[:,a]   grid=B, block=512
// ---------------------------------------------------------------------------
__global__ void h_kernel(const float* __restrict__ hidden,
                         const float* __restrict__ W_h) {
    __shared__ float sh[HID];
    int b = blockIdx.x;
    int a = threadIdx.x;
    sh[a] = hidden[b * HID + a];
    __syncthreads();
    float acc = 0.0f;
#pragma unroll 8
    for (int d = 0; d < HID; d++) acc += sh[d] * W_h[d * ATT + a];
    g_h[b * ATT + a] = acc;
}

// ---------------------------------------------------------------------------
// Score GEMM (fp16 m16n8k16, fp32 accumulate) + tanh/v epilogue.
// CTA tile 128(M) x 128(N), 8 warps (4M x 2N), warp tile 32x64, 256 threads.
// 2 CTAs/SM. A fp32 in smem (AST=40, conflict-free); B pre-permuted fp16.
// 3-stage cp.async pipeline. grid = (4 n-tiles, 1024 m-tiles).
// ---------------------------------------------------------------------------
#define BM 128
#define BN 128
#define BK 32
#define AST 40                        // conflict-free for fragment LDS.64
#define A_TILE (BM * AST)             // 5120 floats / stage (20KB)
#define B_TILE_U (8 * 64 * 4)         // 2048 uints / stage (8KB)
#define NSTAGE (MEMD / BK)            // 16
#define AUX_OFF (3 * A_TILE + 3 * B_TILE_U)
#define SMEM_DYN ((AUX_OFF + 3 * 512) * 4)

__global__ void __launch_bounds__(256, 2) score_mma(
    const float* __restrict__ Amem,
    const float* __restrict__ coverage,
    const float* __restrict__ Wc,
    const float* __restrict__ vvec) {

    extern __shared__ float dsm[];
    float* As_all = dsm;                                      // 3 * A_TILE fp32
    unsigned int* Bs_all = (unsigned int*)(dsm + 3 * A_TILE); // 3 * B_TILE_U
    float* sh_h   = dsm + AUX_OFF;                            // 512 (absolute)
    float* sh_wc  = sh_h + 512;
    float* sh_v   = sh_wc + 512;

    const int tid   = threadIdx.x;
    const int lane  = tid & 31;
    const int wid   = tid >> 5;     // 0..7
    const int warpN = wid & 1;      // 0..1
    const int warpM = wid >> 1;     // 0..3
    const int g     = lane >> 2;    // 0..7
    const int tg    = lane & 3;     // 0..3
    const int chunkB = warpN * 32 + lane;

    const int  n0t  = blockIdx.x;
    const int  n0   = n0t * BN;
    const long row0 = (long)blockIdx.y * BM;
    const int  b    = (int)(row0 >> 12);

    for (int i = tid; i < 512; i += 256) {
        sh_h[i]  = g_h[b * 512 + i];
        sh_wc[i] = Wc[i];
        sh_v[i]  = vvec[i];
    }

    float acc[2][8][4];
#pragma unroll
    for (int i = 0; i < 2; i++)
#pragma unroll
        for (int j = 0; j < 8; j++)
#pragma unroll
            for (int c = 0; c < 4; c++) acc[i][j][c] = 0.0f;

    const unsigned int* BsrcBase = g_Wp16 + (long)n0t * 16 * B_TILE_U;

    auto load_stage = [&](int s) {
        const int buf = s % 3;
        uint32_t Abu = smem_u32(As_all + buf * A_TILE);
        uint32_t Bbu = smem_u32(Bs_all + buf * B_TILE_U);
        const int k0 = s * BK;
        // A: 128 rows x 8 float4 = 1024 cp16 over 256 threads -> 4 each
#pragma unroll
        for (int j = 0; j < 4; j++) {
            int c = tid + 256 * j;
            int r = c >> 3, c4 = c & 7;
            cp16(Abu + (r * AST + c4 * 4) * 4, Amem + (row0 + r) * 512 + k0 + c4 * 4);
        }
        // B: 512 uint4 -> 2 each (coalesced)
        const unsigned int* Bsrc = BsrcBase + (long)s * B_TILE_U;
#pragma unroll
        for (int j = 0; j < 2; j++) {
            int u4 = tid + 256 * j;
            cp16(Bbu + u4 * 16, Bsrc + u4 * 4);
        }
        cp_commit();
    };

    load_stage(0);
    load_stage(1);

    for (int s = 0; s < NSTAGE; s++) {
        if (s < NSTAGE - 1) cp_wait<1>(); else cp_wait<0>();
        __syncthreads();
        if (s + 2 < NSTAGE) load_stage(s + 2);

        const int buf = s % 3;
        const float* Ab = As_all + buf * A_TILE;
        const uint4* B4 = (const uint4*)(Bs_all + buf * B_TILE_U);

#pragma unroll
        for (int kk = 0; kk < 2; kk++) {
            // B fragments: 4x LDS.128 (conflict-free)
            uint4 q0 = B4[(kk * 4 + 0) * 64 + chunkB];  // b0, j0-3
            uint4 q1 = B4[(kk * 4 + 1) * 64 + chunkB];  // b0, j4-7
            uint4 q2 = B4[(kk * 4 + 2) * 64 + chunkB];  // b1, j0-3
            uint4 q3 = B4[(kk * 4 + 3) * 64 + chunkB];  // b1, j4-7
            uint32_t b0[8] = {q0.x, q0.y, q0.z, q0.w, q1.x, q1.y, q1.z, q1.w};
            uint32_t b1[8] = {q2.x, q2.y, q2.z, q2.w, q3.x, q3.y, q3.z, q3.w};

#pragma unroll
            for (int i = 0; i < 2; i++) {
                // A fragments: 4x LDS.64, conflict-free with AST=40
                const int r = warpM * 32 + i * 16 + g;
                const int kbase = kk * 16 + 2 * tg;
                float2 p0 = *(const float2*)(Ab + r * AST + kbase);
                float2 p1 = *(const float2*)(Ab + (r + 8) * AST + kbase);
                float2 p2 = *(const float2*)(Ab + r * AST + kbase + 8);
                float2 p3 = *(const float2*)(Ab + (r + 8) * AST + kbase + 8);
                uint32_t a0 = pack_f16x2(p0);
                uint32_t a1 = pack_f16x2(p1);
                uint32_t a2 = pack_f16x2(p2);
                uint32_t a3 = pack_f16x2(p3);
#pragma unroll
                for (int j = 0; j < 8; j++)
                    mma_f16(acc[i][j], a0, a1, a2, a3, b0[j], b1[j]);
            }
        }
    }

    // ---- epilogue: tanh + v-dot partial over this CTA's 128 n-cols ----
#pragma unroll
    for (int i = 0; i < 2; i++) {
        const int r_lo = warpM * 32 + i * 16 + g;
        const int r_hi = r_lo + 8;
        const float cov_lo = coverage[row0 + r_lo];
        const float cov_hi = coverage[row0 + r_hi];
        float p_lo = 0.0f, p_hi = 0.0f;
#pragma unroll
        for (int j = 0; j < 8; j++) {
            const int nb = n0 + warpN * 64 + j * 8 + tg * 2;  // absolute col
            const float h0 = sh_h[nb + 0], h1 = sh_h[nb + 1];
            const float w0 = sh_wc[nb + 0], w1 = sh_wc[nb + 1];
            const float v0 = sh_v[nb + 0], v1 = sh_v[nb + 1];
            p_lo += tanh_fast(acc[i][j][0] + h0 + cov_lo * w0) * v0;
            p_lo += tanh_fast(acc[i][j][1] + h1 + cov_lo * w1) * v1;
            p_hi += tanh_fast(acc[i][j][2] + h0 + cov_hi * w0) * v0;
            p_hi += tanh_fast(acc[i][j][3] + h1 + cov_hi * w1) * v1;
        }
        p_lo += __shfl_xor_sync(0xffffffffu, p_lo, 1);
        p_lo += __shfl_xor_sync(0xffffffffu, p_lo, 2);
        p_hi += __shfl_xor_sync(0xffffffffu, p_hi, 1);
        p_hi += __shfl_xor_sync(0xffffffffu, p_hi, 2);
        if (tg == 0) {
            atomicAdd(&g_scores[row0 + r_lo], p_lo);
            atomicAdd(&g_scores[row0 + r_hi], p_hi);
        }
    }
}

// ---------------------------------------------------------------------------
// Softmax over S per batch (with pad mask). grid=B, block=1024.
// ---------------------------------------------------------------------------
__global__ void softmax_kernel(const unsigned char* __restrict__ pad,
                               float* __restrict__ attn) {
    __shared__ float red[1024];
    const int b = blockIdx.x;
    const int tid = threadIdx.x;

    float mx = -INFINITY;
    for (int s = tid; s < SS; s += 1024) {
        float sc = pad[b * SS + s] ? -INFINITY : g_scores[b * SS + s];
        mx = fmaxf(mx, sc);
    }
    red[tid] = mx;
    __syncthreads();
    for (int off = 512; off > 0; off >>= 1) {
        if (tid < off) red[tid] = fmaxf(red[tid], red[tid + off]);
        __syncthreads();
    }
    mx = red[0];
    __syncthreads();

    float sum = 0.0f;
    for (int s = tid; s < SS; s += 1024) {
        float sc = pad[b * SS + s] ? -INFINITY : g_scores[b * SS + s];
        float e = expf(sc - mx);
        attn[b * SS + s] = e;
        sum += e;
    }
    red[tid] = sum;
    __syncthreads();
    for (int off = 512; off > 0; off >>= 1) {
        if (tid < off) red[tid] += red[tid + off];
        __syncthreads();
    }
    float inv = 1.0f / red[0];
    for (int s = tid; s < SS; s += 1024) attn[b * SS + s] *= inv;
}

// ---------------------------------------------------------------------------
// context[b][d] = sum_s attn[b][s] * memory[b][s][d].
// grid=(B,32), block=128. Each thread owns 4 consecutive d (float4 loads).
// ---------------------------------------------------------------------------
__global__ void context_kernel(const float* __restrict__ memory,
                               const float* __restrict__ attn,
                               float* __restrict__ ctx) {
    __shared__ float w[128];
    const int b = blockIdx.x;
    const int s0 = blockIdx.y * 128;
    const int t = threadIdx.x;          // 0..127
    const int d = t * 4;

    w[t] = attn[b * SS + s0 + t];
    __syncthreads();

    float4 acc = make_float4(0.f, 0.f, 0.f, 0.f);
    const float* mbase = memory + ((long)b * SS + s0) * MEMD + d;
#pragma unroll 4
    for (int s = 0; s < 128; s++) {
        float4 m = *reinterpret_cast<const float4*>(mbase + (long)s * MEMD);
        float ws = w[s];
        acc.x += ws * m.x;
        acc.y += ws * m.y;
        acc.z += ws * m.z;
        acc.w += ws * m.w;
    }
    atomicAdd(&ctx[b * MEMD + d + 0], acc.x);
    atomicAdd(&ctx[b * MEMD + d + 1], acc.y);
    atomicAdd(&ctx[b * MEMD + d + 2], acc.z);
    atomicAdd(&ctx[b * MEMD + d + 3], acc.w);
}

// ---------------------------------------------------------------------------
// Launch.  Inputs (metadata order):
//   0 hidden | 1 memory | 2 mem_pad | 3 coverage | 4 W_h | 5 W_m | 6 W_c | 7 v
// Output: [context (B*MEM) | attn (B*S)] f32
// ---------------------------------------------------------------------------
extern "C" void kernel_launch(void* const* d_in, const int* in_sizes, int n_in,
                              void* d_out, int out_size) {
    const float* hidden   = (const float*)d_in[0];
    const float* memory   = (const float*)d_in[1];
    const unsigned char* mem_pad = (const unsigned char*)d_in[2];
    const float* coverage = (const float*)d_in[3];
    const float* W_h      = (const float*)d_in[4];
    const float* W_m      = (const float*)d_in[5];
    const float* W_c      = (const float*)d_in[6];
    const float* v        = (const float*)d_in[7];

    float* out = (float*)d_out;
    float* out_ctx  = out;
    float* out_attn = out + BB * MEMD;

    cudaFuncSetAttribute(score_mma, cudaFuncAttributeMaxDynamicSharedMemorySize,
                         SMEM_DYN);

    zero_kernel<<<(BB * SS + 255) / 256, 256>>>(out_ctx);
    permute_wm16<<<(4 * 16 * 8 * 64 * 4 + 255) / 256, 256>>>(W_m);
    h_kernel<<<BB, 512>>>(hidden, W_h);
    {
        dim3 grid(ATT / BN, BB * SS / BM);
        score_mma<<<grid, 256, SMEM_DYN>>>(memory, coverage, W_c, v);
    }
    softmax_kernel<<<BB, 1024>>>(mem_pad, out_attn);
    {
        dim3 grid(BB, SS / 128);
        context_kernel<<<grid, 128>>>(memory, out_attn, out_ctx);
    }
}

// round 16
// speedup vs baseline: 1.1271x; 1.0051x over previous
#include <cuda_runtime.h>
#include <cuda_fp16.h>
#include <math.h>
#include <stdint.h>

#define BB   32
#define SS   4096
#define HID  512
#define MEMD 512
#define ATT  512

// ------------------------------- scratch -----------------------------------
__device__ float g_scores[BB * SS];
__device__ float g_h[BB * ATT];
// W_m permuted into per-thread fp16 fragment order for m16n8k16, BN=128 tiles.
// uint (half2) layout: [n0t(4)][stage(16)][i8(8)][chunk(64)][e(4)]
//   i8 = kk*4 + kb*2 + jq ; j = jq*4 + e ; chunk = warpN*32 + lane
//   half2 = { W[k][n], W[k+1][n] },  k = s*32 + kk*16 + kb*8 + 2*tg
//   n = n0t*128 + warpN*64 + j*8 + g
__device__ unsigned int g_Wp16[4 * 16 * 8 * 64 * 4];

// ------------------------------- helpers -----------------------------------
__device__ __forceinline__ uint32_t smem_u32(const void* p) {
    return (uint32_t)__cvta_generic_to_shared(p);
}
__device__ __forceinline__ void cp16(uint32_t dst, const void* src) {
    asm volatile("cp.async.cg.shared.global [%0], [%1], 16;\n" :: "r"(dst), "l"(src));
}
__device__ __forceinline__ void cp_commit() { asm volatile("cp.async.commit_group;\n" ::: "memory"); }
template <int N>
__device__ __forceinline__ void cp_wait() {
    asm volatile("cp.async.wait_group %0;\n" :: "n"(N) : "memory");
}
// pack float2 {x=k_even, y=k_odd} -> f16x2 reg (lo = x)
__device__ __forceinline__ uint32_t pack_f16x2(float2 p) {
    uint32_t d;
    asm("cvt.rn.f16x2.f32 %0, %1, %2;" : "=r"(d) : "f"(p.y), "f"(p.x));
    return d;
}
__device__ __forceinline__ void mma_f16(float* d, uint32_t a0, uint32_t a1,
                                        uint32_t a2, uint32_t a3,
                                        uint32_t b0, uint32_t b1) {
    asm volatile(
        "mma.sync.aligned.m16n8k16.row.col.f32.f16.f16.f32 "
        "{%0,%1,%2,%3}, {%4,%5,%6,%7}, {%8,%9}, {%0,%1,%2,%3};"
        : "+f"(d[0]), "+f"(d[1]), "+f"(d[2]), "+f"(d[3])
        : "r"(a0), "r"(a1), "r"(a2), "r"(a3), "r"(b0), "r"(b1));
}
__device__ __forceinline__ float tanh_fast(float x) {
    float y; asm("tanh.approx.f32 %0, %1;" : "=f"(y) : "f"(x)); return y;
}

// ---------------------------------------------------------------------------
// Build g_Wp16 (fp16 permuted fragment layout, BN=128). One thread per half2.
// Also zeroes g_scores (131072 threads == BB*SS exactly).
// ---------------------------------------------------------------------------
__global__ void permute_wm16(const float* __restrict__ Wm) {
    int o = blockIdx.x * blockDim.x + threadIdx.x;
    if (o >= 4 * 16 * 8 * 64 * 4) return;
    g_scores[o] = 0.0f;
    int e     = o & 3;
    int chunk = (o >> 2) & 63;
    int i8    = (o >> 8) & 7;
    int s     = (o >> 11) & 15;
    int n0t   = o >> 15;
    int kk = i8 >> 2, kb = (i8 >> 1) & 1, jq = i8 & 1;
    int j = jq * 4 + e;
    int lane = chunk & 31, warpN = chunk >> 5;
    int g = lane >> 2, tg = lane & 3;
    int k = s * 32 + kk * 16 + kb * 8 + 2 * tg;
    int n = n0t * 128 + warpN * 64 + j * 8 + g;
    __half2 h = __floats2half2_rn(Wm[k * ATT + n], Wm[(k + 1) * ATT + n]);
    g_Wp16[o] = *reinterpret_cast<unsigned int*>(&h);
}

// ---------------------------------------------------------------------------
// h[b][a] = hidden[b] . W_h[:,a]   grid=B, block=512. Also zeroes out_ctx.
// ---------------------------------------------------------------------------
__global__ void h_kernel(const float* __restrict__ hidden,
                         const float* __restrict__ W_h,
                         float* __restrict__ out_ctx) {
    __shared__ float sh[HID];
    int b = blockIdx.x;
    int a = threadIdx.x;
    sh[a] = hidden[b * HID + a];
    out_ctx[b * MEMD + a] = 0.0f;
    __syncthreads();
    float acc = 0.0f;
#pragma unroll 8
    for (int d = 0; d < HID; d++) acc += sh[d] * W_h[d * ATT + a];
    g_h[b * ATT + a] = acc;
}

// ---------------------------------------------------------------------------
// Score GEMM (fp16 m16n8k16, fp32 accumulate) + tanh/v epilogue.
// CTA tile 128(M) x 128(N), 8 warps (4M x 2N), warp tile 32x64, 256 threads.
// 2 CTAs/SM. A fp32 in smem (AST=40, conflict-free); B pre-permuted fp16.
// 3-stage cp.async pipeline. grid = (4 n-tiles, 1024 m-tiles).
// *** Proven 237us version — DO NOT MODIFY. ***
// ---------------------------------------------------------------------------
#define BM 128
#define BN 128
#define BK 32
#define AST 40                        // conflict-free for fragment LDS.64
#define A_TILE (BM * AST)             // 5120 floats / stage (20KB)
#define B_TILE_U (8 * 64 * 4)         // 2048 uints / stage (8KB)
#define NSTAGE (MEMD / BK)            // 16
#define AUX_OFF (3 * A_TILE + 3 * B_TILE_U)
#define SMEM_DYN ((AUX_OFF + 3 * 512) * 4)

__global__ void __launch_bounds__(256, 2) score_mma(
    const float* __restrict__ Amem,
    const float* __restrict__ coverage,
    const float* __restrict__ Wc,
    const float* __restrict__ vvec) {

    extern __shared__ float dsm[];
    float* As_all = dsm;                                      // 3 * A_TILE fp32
    unsigned int* Bs_all = (unsigned int*)(dsm + 3 * A_TILE); // 3 * B_TILE_U
    float* sh_h   = dsm + AUX_OFF;                            // 512 (absolute)
    float* sh_wc  = sh_h + 512;
    float* sh_v   = sh_wc + 512;

    const int tid   = threadIdx.x;
    const int lane  = tid & 31;
    const int wid   = tid >> 5;     // 0..7
    const int warpN = wid & 1;      // 0..1
    const int warpM = wid >> 1;     // 0..3
    const int g     = lane >> 2;    // 0..7
    const int tg    = lane & 3;     // 0..3
    const int chunkB = warpN * 32 + lane;

    const int  n0t  = blockIdx.x;
    const int  n0   = n0t * BN;
    const long row0 = (long)blockIdx.y * BM;
    const int  b    = (int)(row0 >> 12);

    for (int i = tid; i < 512; i += 256) {
        sh_h[i]  = g_h[b * 512 + i];
        sh_wc[i] = Wc[i];
        sh_v[i]  = vvec[i];
    }

    float acc[2][8][4];
#pragma unroll
    for (int i = 0; i < 2; i++)
#pragma unroll
        for (int j = 0; j < 8; j++)
#pragma unroll
            for (int c = 0; c < 4; c++) acc[i][j][c] = 0.0f;

    const unsigned int* BsrcBase = g_Wp16 + (long)n0t * 16 * B_TILE_U;

    auto load_stage = [&](int s) {
        const int buf = s % 3;
        uint32_t Abu = smem_u32(As_all + buf * A_TILE);
        uint32_t Bbu = smem_u32(Bs_all + buf * B_TILE_U);
        const int k0 = s * BK;
        // A: 128 rows x 8 float4 = 1024 cp16 over 256 threads -> 4 each
#pragma unroll
        for (int j = 0; j < 4; j++) {
            int c = tid + 256 * j;
            int r = c >> 3, c4 = c & 7;
            cp16(Abu + (r * AST + c4 * 4) * 4, Amem + (row0 + r) * 512 + k0 + c4 * 4);
        }
        // B: 512 uint4 -> 2 each (coalesced)
        const unsigned int* Bsrc = BsrcBase + (long)s * B_TILE_U;
#pragma unroll
        for (int j = 0; j < 2; j++) {
            int u4 = tid + 256 * j;
            cp16(Bbu + u4 * 16, Bsrc + u4 * 4);
        }
        cp_commit();
    };

    load_stage(0);
    load_stage(1);

    for (int s = 0; s < NSTAGE; s++) {
        if (s < NSTAGE - 1) cp_wait<1>(); else cp_wait<0>();
        __syncthreads();
        if (s + 2 < NSTAGE) load_stage(s + 2);

        const int buf = s % 3;
        const float* Ab = As_all + buf * A_TILE;
        const uint4* B4 = (const uint4*)(Bs_all + buf * B_TILE_U);

#pragma unroll
        for (int kk = 0; kk < 2; kk++) {
            // B fragments: 4x LDS.128 (conflict-free)
            uint4 q0 = B4[(kk * 4 + 0) * 64 + chunkB];  // b0, j0-3
            uint4 q1 = B4[(kk * 4 + 1) * 64 + chunkB];  // b0, j4-7
            uint4 q2 = B4[(kk * 4 + 2) * 64 + chunkB];  // b1, j0-3
            uint4 q3 = B4[(kk * 4 + 3) * 64 + chunkB];  // b1, j4-7
            uint32_t b0[8] = {q0.x, q0.y, q0.z, q0.w, q1.x, q1.y, q1.z, q1.w};
            uint32_t b1[8] = {q2.x, q2.y, q2.z, q2.w, q3.x, q3.y, q3.z, q3.w};

#pragma unroll
            for (int i = 0; i < 2; i++) {
                // A fragments: 4x LDS.64, conflict-free with AST=40
                const int r = warpM * 32 + i * 16 + g;
                const int kbase = kk * 16 + 2 * tg;
                float2 p0 = *(const float2*)(Ab + r * AST + kbase);
                float2 p1 = *(const float2*)(Ab + (r + 8) * AST + kbase);
                float2 p2 = *(const float2*)(Ab + r * AST + kbase + 8);
                float2 p3 = *(const float2*)(Ab + (r + 8) * AST + kbase + 8);
                uint32_t a0 = pack_f16x2(p0);
                uint32_t a1 = pack_f16x2(p1);
                uint32_t a2 = pack_f16x2(p2);
                uint32_t a3 = pack_f16x2(p3);
#pragma unroll
                for (int j = 0; j < 8; j++)
                    mma_f16(acc[i][j], a0, a1, a2, a3, b0[j], b1[j]);
            }
        }
    }

    // ---- epilogue: tanh + v-dot partial over this CTA's 128 n-cols ----
#pragma unroll
    for (int i = 0; i < 2; i++) {
        const int r_lo = warpM * 32 + i * 16 + g;
        const int r_hi = r_lo + 8;
        const float cov_lo = coverage[row0 + r_lo];
        const float cov_hi = coverage[row0 + r_hi];
        float p_lo = 0.0f, p_hi = 0.0f;
#pragma unroll
        for (int j = 0; j < 8; j++) {
            const int nb = n0 + warpN * 64 + j * 8 + tg * 2;  // absolute col
            const float h0 = sh_h[nb + 0], h1 = sh_h[nb + 1];
            const float w0 = sh_wc[nb + 0], w1 = sh_wc[nb + 1];
            const float v0 = sh_v[nb + 0], v1 = sh_v[nb + 1];
            p_lo += tanh_fast(acc[i][j][0] + h0 + cov_lo * w0) * v0;
            p_lo += tanh_fast(acc[i][j][1] + h1 + cov_lo * w1) * v1;
            p_hi += tanh_fast(acc[i][j][2] + h0 + cov_hi * w0) * v0;
            p_hi += tanh_fast(acc[i][j][3] + h1 + cov_hi * w1) * v1;
        }
        p_lo += __shfl_xor_sync(0xffffffffu, p_lo, 1);
        p_lo += __shfl_xor_sync(0xffffffffu, p_lo, 2);
        p_hi += __shfl_xor_sync(0xffffffffu, p_hi, 1);
        p_hi += __shfl_xor_sync(0xffffffffu, p_hi, 2);
        if (tg == 0) {
            atomicAdd(&g_scores[row0 + r_lo], p_lo);
            atomicAdd(&g_scores[row0 + r_hi], p_hi);
        }
    }
}

// ---------------------------------------------------------------------------
// Softmax over S per batch (with pad mask). grid=B, block=1024.
// ---------------------------------------------------------------------------
__global__ void softmax_kernel(const unsigned char* __restrict__ pad,
                               float* __restrict__ attn) {
    __shared__ float red[1024];
    const int b = blockIdx.x;
    const int tid = threadIdx.x;

    float mx = -INFINITY;
    for (int s = tid; s < SS; s += 1024) {
        float sc = pad[b * SS + s] ? -INFINITY : g_scores[b * SS + s];
        mx = fmaxf(mx, sc);
    }
    red[tid] = mx;
    __syncthreads();
    for (int off = 512; off > 0; off >>= 1) {
        if (tid < off) red[tid] = fmaxf(red[tid], red[tid + off]);
        __syncthreads();
    }
    mx = red[0];
    __syncthreads();

    float sum = 0.0f;
    for (int s = tid; s < SS; s += 1024) {
        float sc = pad[b * SS + s] ? -INFINITY : g_scores[b * SS + s];
        float e = expf(sc - mx);
        attn[b * SS + s] = e;
        sum += e;
    }
    red[tid] = sum;
    __syncthreads();
    for (int off = 512; off > 0; off >>= 1) {
        if (tid < off) red[tid] += red[tid + off];
        __syncthreads();
    }
    float inv = 1.0f / red[0];
    for (int s = tid; s < SS; s += 1024) attn[b * SS + s] *= inv;
}

// ---------------------------------------------------------------------------
// context[b][d] = sum_s attn[b][s] * memory[b][s][d].
// grid=(B,64), block=128, s-chunk 64. Each thread owns 4 consecutive d.
// ---------------------------------------------------------------------------
__global__ void context_kernel(const float* __restrict__ memory,
                               const float* __restrict__ attn,
                               float* __restrict__ ctx) {
    __shared__ float w[64];
    const int b = blockIdx.x;
    const int s0 = blockIdx.y * 64;
    const int t = threadIdx.x;          // 0..127
    const int d = t * 4;

    if (t < 64) w[t] = attn[b * SS + s0 + t];
    __syncthreads();

    float4 acc = make_float4(0.f, 0.f, 0.f, 0.f);
    const float* mbase = memory + ((long)b * SS + s0) * MEMD + d;
#pragma unroll 8
    for (int s = 0; s < 64; s++) {
        float4 m = *reinterpret_cast<const float4*>(mbase + (long)s * MEMD);
        float ws = w[s];
        acc.x += ws * m.x;
        acc.y += ws * m.y;
        acc.z += ws * m.z;
        acc.w += ws * m.w;
    }
    atomicAdd(&ctx[b * MEMD + d + 0], acc.x);
    atomicAdd(&ctx[b * MEMD + d + 1], acc.y);
    atomicAdd(&ctx[b * MEMD + d + 2], acc.z);
    atomicAdd(&ctx[b * MEMD + d + 3], acc.w);
}

// ---------------------------------------------------------------------------
// Launch.  Inputs (metadata order):
//   0 hidden | 1 memory | 2 mem_pad | 3 coverage | 4 W_h | 5 W_m | 6 W_c | 7 v
// Output: [context (B*MEM) | attn (B*S)] f32
// ---------------------------------------------------------------------------
extern "C" void kernel_launch(void* const* d_in, const int* in_sizes, int n_in,
                              void* d_out, int out_size) {
    const float* hidden   = (const float*)d_in[0];
    const float* memory   = (const float*)d_in[1];
    const unsigned char* mem_pad = (const unsigned char*)d_in[2];
    const float* coverage = (const float*)d_in[3];
    const float* W_h      = (const float*)d_in[4];
    const float* W_m      = (const float*)d_in[5];
    const float* W_c      = (const float*)d_in[6];
    const float* v        = (const float*)d_in[7];

    float* out = (float*)d_out;
    float* out_ctx  = out;
    float* out_attn = out + BB * MEMD;

    cudaFuncSetAttribute(score_mma, cudaFuncAttributeMaxDynamicSharedMemorySize,
                         SMEM_DYN);

    permute_wm16<<<(4 * 16 * 8 * 64 * 4 + 255) / 256, 256>>>(W_m);
    h_kernel<<<BB, 512>>>(hidden, W_h, out_ctx);
    {
        dim3 grid(ATT / BN, BB * SS / BM);
        score_mma<<<grid, 256, SMEM_DYN>>>(memory, coverage, W_c, v);
    }
    softmax_kernel<<<BB, 1024>>>(mem_pad, out_attn);
    {
        dim3 grid(BB, SS / 64);
        context_kernel<<<grid, 128>>>(memory, out_attn, out_ctx);
    }
}

// round 17
// speedup vs baseline: 1.1419x; 1.0132x over previous
#include <cuda_runtime.h>
#include <cuda_fp16.h>
#include <math.h>
#include <stdint.h>

#define BB   32
#define SS   4096
#define HID  512
#define MEMD 512
#define ATT  512

// ------------------------------- scratch -----------------------------------
__device__ float g_scores[BB * SS];
__device__ float g_h[BB * ATT];
__device__ float2 g_stat[BB];           // per-batch (max, 1/sum)
// W_m permuted into per-thread fp16 fragment order for m16n8k16, BN=128 tiles.
// uint (half2) layout: [n0t(4)][stage(16)][i8(8)][chunk(64)][e(4)]
//   i8 = kk*4 + kb*2 + jq ; j = jq*4 + e ; chunk = warpN*32 + lane
//   half2 = { W[k][n], W[k+1][n] },  k = s*32 + kk*16 + kb*8 + 2*tg
//   n = n0t*128 + warpN*64 + j*8 + g
__device__ unsigned int g_Wp16[4 * 16 * 8 * 64 * 4];

// ------------------------------- helpers -----------------------------------
__device__ __forceinline__ uint32_t smem_u32(const void* p) {
    return (uint32_t)__cvta_generic_to_shared(p);
}
__device__ __forceinline__ void cp16(uint32_t dst, const void* src) {
    asm volatile("cp.async.cg.shared.global [%0], [%1], 16;\n" :: "r"(dst), "l"(src));
}
__device__ __forceinline__ void cp_commit() { asm volatile("cp.async.commit_group;\n" ::: "memory"); }
template <int N>
__device__ __forceinline__ void cp_wait() {
    asm volatile("cp.async.wait_group %0;\n" :: "n"(N) : "memory");
}
// pack float2 {x=k_even, y=k_odd} -> f16x2 reg (lo = x)
__device__ __forceinline__ uint32_t pack_f16x2(float2 p) {
    uint32_t d;
    asm("cvt.rn.f16x2.f32 %0, %1, %2;" : "=r"(d) : "f"(p.y), "f"(p.x));
    return d;
}
__device__ __forceinline__ void mma_f16(float* d, uint32_t a0, uint32_t a1,
                                        uint32_t a2, uint32_t a3,
                                        uint32_t b0, uint32_t b1) {
    asm volatile(
        "mma.sync.aligned.m16n8k16.row.col.f32.f16.f16.f32 "
        "{%0,%1,%2,%3}, {%4,%5,%6,%7}, {%8,%9}, {%0,%1,%2,%3};"
        : "+f"(d[0]), "+f"(d[1]), "+f"(d[2]), "+f"(d[3])
        : "r"(a0), "r"(a1), "r"(a2), "r"(a3), "r"(b0), "r"(b1));
}
__device__ __forceinline__ float tanh_fast(float x) {
    float y; asm("tanh.approx.f32 %0, %1;" : "=f"(y) : "f"(x)); return y;
}

// ---------------------------------------------------------------------------
// Build g_Wp16 (fp16 permuted fragment layout, BN=128). One thread per half2.
// Also zeroes g_scores (131072 threads == BB*SS exactly).
// ---------------------------------------------------------------------------
__global__ void permute_wm16(const float* __restrict__ Wm) {
    int o = blockIdx.x * blockDim.x + threadIdx.x;
    if (o >= 4 * 16 * 8 * 64 * 4) return;
    g_scores[o] = 0.0f;
    int e     = o & 3;
    int chunk = (o >> 2) & 63;
    int i8    = (o >> 8) & 7;
    int s     = (o >> 11) & 15;
    int n0t   = o >> 15;
    int kk = i8 >> 2, kb = (i8 >> 1) & 1, jq = i8 & 1;
    int j = jq * 4 + e;
    int lane = chunk & 31, warpN = chunk >> 5;
    int g = lane >> 2, tg = lane & 3;
    int k = s * 32 + kk * 16 + kb * 8 + 2 * tg;
    int n = n0t * 128 + warpN * 64 + j * 8 + g;
    __half2 h = __floats2half2_rn(Wm[k * ATT + n], Wm[(k + 1) * ATT + n]);
    g_Wp16[o] = *reinterpret_cast<unsigned int*>(&h);
}

// ---------------------------------------------------------------------------
// h[b][a] = hidden[b] . W_h[:,a]   grid=B, block=512. Also zeroes out_ctx.
// ---------------------------------------------------------------------------
__global__ void h_kernel(const float* __restrict__ hidden,
                         const float* __restrict__ W_h,
                         float* __restrict__ out_ctx) {
    __shared__ float sh[HID];
    int b = blockIdx.x;
    int a = threadIdx.x;
    sh[a] = hidden[b * HID + a];
    out_ctx[b * MEMD + a] = 0.0f;
    __syncthreads();
    float acc = 0.0f;
#pragma unroll 8
    for (int d = 0; d < HID; d++) acc += sh[d] * W_h[d * ATT + a];
    g_h[b * ATT + a] = acc;
}

// ---------------------------------------------------------------------------
// Score GEMM (fp16 m16n8k16, fp32 accumulate) + tanh/v epilogue.
// CTA tile 128(M) x 128(N), 8 warps (4M x 2N), warp tile 32x64, 256 threads.
// 2 CTAs/SM. A fp32 in smem (AST=40, conflict-free); B pre-permuted fp16.
// 3-stage cp.async pipeline. grid = (4 n-tiles, 1024 m-tiles).
// *** Proven 237us version — DO NOT MODIFY. ***
// ---------------------------------------------------------------------------
#define BM 128
#define BN 128
#define BK 32
#define AST 40                        // conflict-free for fragment LDS.64
#define A_TILE (BM * AST)             // 5120 floats / stage (20KB)
#define B_TILE_U (8 * 64 * 4)         // 2048 uints / stage (8KB)
#define NSTAGE (MEMD / BK)            // 16
#define AUX_OFF (3 * A_TILE + 3 * B_TILE_U)
#define SMEM_DYN ((AUX_OFF + 3 * 512) * 4)

__global__ void __launch_bounds__(256, 2) score_mma(
    const float* __restrict__ Amem,
    const float* __restrict__ coverage,
    const float* __restrict__ Wc,
    const float* __restrict__ vvec) {

    extern __shared__ float dsm[];
    float* As_all = dsm;                                      // 3 * A_TILE fp32
    unsigned int* Bs_all = (unsigned int*)(dsm + 3 * A_TILE); // 3 * B_TILE_U
    float* sh_h   = dsm + AUX_OFF;                            // 512 (absolute)
    float* sh_wc  = sh_h + 512;
    float* sh_v   = sh_wc + 512;

    const int tid   = threadIdx.x;
    const int lane  = tid & 31;
    const int wid   = tid >> 5;     // 0..7
    const int warpN = wid & 1;      // 0..1
    const int warpM = wid >> 1;     // 0..3
    const int g     = lane >> 2;    // 0..7
    const int tg    = lane & 3;     // 0..3
    const int chunkB = warpN * 32 + lane;

    const int  n0t  = blockIdx.x;
    const int  n0   = n0t * BN;
    const long row0 = (long)blockIdx.y * BM;
    const int  b    = (int)(row0 >> 12);

    for (int i = tid; i < 512; i += 256) {
        sh_h[i]  = g_h[b * 512 + i];
        sh_wc[i] = Wc[i];
        sh_v[i]  = vvec[i];
    }

    float acc[2][8][4];
#pragma unroll
    for (int i = 0; i < 2; i++)
#pragma unroll
        for (int j = 0; j < 8; j++)
#pragma unroll
            for (int c = 0; c < 4; c++) acc[i][j][c] = 0.0f;

    const unsigned int* BsrcBase = g_Wp16 + (long)n0t * 16 * B_TILE_U;

    auto load_stage = [&](int s) {
        const int buf = s % 3;
        uint32_t Abu = smem_u32(As_all + buf * A_TILE);
        uint32_t Bbu = smem_u32(Bs_all + buf * B_TILE_U);
        const int k0 = s * BK;
        // A: 128 rows x 8 float4 = 1024 cp16 over 256 threads -> 4 each
#pragma unroll
        for (int j = 0; j < 4; j++) {
            int c = tid + 256 * j;
            int r = c >> 3, c4 = c & 7;
            cp16(Abu + (r * AST + c4 * 4) * 4, Amem + (row0 + r) * 512 + k0 + c4 * 4);
        }
        // B: 512 uint4 -> 2 each (coalesced)
        const unsigned int* Bsrc = BsrcBase + (long)s * B_TILE_U;
#pragma unroll
        for (int j = 0; j < 2; j++) {
            int u4 = tid + 256 * j;
            cp16(Bbu + u4 * 16, Bsrc + u4 * 4);
        }
        cp_commit();
    };

    load_stage(0);
    load_stage(1);

    for (int s = 0; s < NSTAGE; s++) {
        if (s < NSTAGE - 1) cp_wait<1>(); else cp_wait<0>();
        __syncthreads();
        if (s + 2 < NSTAGE) load_stage(s + 2);

        const int buf = s % 3;
        const float* Ab = As_all + buf * A_TILE;
        const uint4* B4 = (const uint4*)(Bs_all + buf * B_TILE_U);

#pragma unroll
        for (int kk = 0; kk < 2; kk++) {
            // B fragments: 4x LDS.128 (conflict-free)
            uint4 q0 = B4[(kk * 4 + 0) * 64 + chunkB];  // b0, j0-3
            uint4 q1 = B4[(kk * 4 + 1) * 64 + chunkB];  // b0, j4-7
            uint4 q2 = B4[(kk * 4 + 2) * 64 + chunkB];  // b1, j0-3
            uint4 q3 = B4[(kk * 4 + 3) * 64 + chunkB];  // b1, j4-7
            uint32_t b0[8] = {q0.x, q0.y, q0.z, q0.w, q1.x, q1.y, q1.z, q1.w};
            uint32_t b1[8] = {q2.x, q2.y, q2.z, q2.w, q3.x, q3.y, q3.z, q3.w};

#pragma unroll
            for (int i = 0; i < 2; i++) {
                // A fragments: 4x LDS.64, conflict-free with AST=40
                const int r = warpM * 32 + i * 16 + g;
                const int kbase = kk * 16 + 2 * tg;
                float2 p0 = *(const float2*)(Ab + r * AST + kbase);
                float2 p1 = *(const float2*)(Ab + (r + 8) * AST + kbase);
                float2 p2 = *(const float2*)(Ab + r * AST + kbase + 8);
                float2 p3 = *(const float2*)(Ab + (r + 8) * AST + kbase + 8);
                uint32_t a0 = pack_f16x2(p0);
                uint32_t a1 = pack_f16x2(p1);
                uint32_t a2 = pack_f16x2(p2);
                uint32_t a3 = pack_f16x2(p3);
#pragma unroll
                for (int j = 0; j < 8; j++)
                    mma_f16(acc[i][j], a0, a1, a2, a3, b0[j], b1[j]);
            }
        }
    }

    // ---- epilogue: tanh + v-dot partial over this CTA's 128 n-cols ----
#pragma unroll
    for (int i = 0; i < 2; i++) {
        const int r_lo = warpM * 32 + i * 16 + g;
        const int r_hi = r_lo + 8;
        const float cov_lo = coverage[row0 + r_lo];
        const float cov_hi = coverage[row0 + r_hi];
        float p_lo = 0.0f, p_hi = 0.0f;
#pragma unroll
        for (int j = 0; j < 8; j++) {
            const int nb = n0 + warpN * 64 + j * 8 + tg * 2;  // absolute col
            const float h0 = sh_h[nb + 0], h1 = sh_h[nb + 1];
            const float w0 = sh_wc[nb + 0], w1 = sh_wc[nb + 1];
            const float v0 = sh_v[nb + 0], v1 = sh_v[nb + 1];
            p_lo += tanh_fast(acc[i][j][0] + h0 + cov_lo * w0) * v0;
            p_lo += tanh_fast(acc[i][j][1] + h1 + cov_lo * w1) * v1;
            p_hi += tanh_fast(acc[i][j][2] + h0 + cov_hi * w0) * v0;
            p_hi += tanh_fast(acc[i][j][3] + h1 + cov_hi * w1) * v1;
        }
        p_lo += __shfl_xor_sync(0xffffffffu, p_lo, 1);
        p_lo += __shfl_xor_sync(0xffffffffu, p_lo, 2);
        p_hi += __shfl_xor_sync(0xffffffffu, p_hi, 1);
        p_hi += __shfl_xor_sync(0xffffffffu, p_hi, 2);
        if (tg == 0) {
            atomicAdd(&g_scores[row0 + r_lo], p_lo);
            atomicAdd(&g_scores[row0 + r_hi], p_hi);
        }
    }
}

// ---------------------------------------------------------------------------
// Softmax reduce: per-batch (max, 1/sum) into g_stat. grid=B, block=1024.
// float4 / uchar4 vectorized (each thread handles exactly 4 s).
// ---------------------------------------------------------------------------
__global__ void softmax_reduce(const unsigned char* __restrict__ pad) {
    __shared__ float red[1024];
    const int b = blockIdx.x;
    const int tid = threadIdx.x;

    float4 v = reinterpret_cast<const float4*>(g_scores + b * SS)[tid];
    uchar4 p = reinterpret_cast<const uchar4*>(pad + b * SS)[tid];
    if (p.x) v.x = -INFINITY;
    if (p.y) v.y = -INFINITY;
    if (p.z) v.z = -INFINITY;
    if (p.w) v.w = -INFINITY;

    float mx = fmaxf(fmaxf(v.x, v.y), fmaxf(v.z, v.w));
    red[tid] = mx;
    __syncthreads();
    for (int off = 512; off > 0; off >>= 1) {
        if (tid < off) red[tid] = fmaxf(red[tid], red[tid + off]);
        __syncthreads();
    }
    mx = red[0];
    __syncthreads();

    float sum = expf(v.x - mx) + expf(v.y - mx) + expf(v.z - mx) + expf(v.w - mx);
    red[tid] = sum;
    __syncthreads();
    for (int off = 512; off > 0; off >>= 1) {
        if (tid < off) red[tid] += red[tid + off];
        __syncthreads();
    }
    if (tid == 0) g_stat[b] = make_float2(mx, 1.0f / red[0]);
}

// ---------------------------------------------------------------------------
// Context + attn write. grid=(B, 64), block=128, s-chunk 64.
// Computes attn weights on the fly from g_scores + g_stat; writes attn for
// its chunk (each s owned by exactly one CTA) and accumulates ctx (float4).
// ---------------------------------------------------------------------------
__global__ void context_kernel(const float* __restrict__ memory,
                               const unsigned char* __restrict__ pad,
                               float* __restrict__ attn,
                               float* __restrict__ ctx) {
    __shared__ float w[64];
    const int b = blockIdx.x;
    const int s0 = blockIdx.y * 64;
    const int t = threadIdx.x;          // 0..127
    const int d = t * 4;

    const float2 st = g_stat[b];
    if (t < 64) {
        const long idx = (long)b * SS + s0 + t;
        float sc = pad[idx] ? -INFINITY : g_scores[idx];
        float e = expf(sc - st.x) * st.y;
        attn[idx] = e;
        w[t] = e;
    }
    __syncthreads();

    float4 acc = make_float4(0.f, 0.f, 0.f, 0.f);
    const float* mbase = memory + ((long)b * SS + s0) * MEMD + d;
#pragma unroll 8
    for (int s = 0; s < 64; s++) {
        float4 m = *reinterpret_cast<const float4*>(mbase + (long)s * MEMD);
        float ws = w[s];
        acc.x += ws * m.x;
        acc.y += ws * m.y;
        acc.z += ws * m.z;
        acc.w += ws * m.w;
    }
    atomicAdd(&ctx[b * MEMD + d + 0], acc.x);
    atomicAdd(&ctx[b * MEMD + d + 1], acc.y);
    atomicAdd(&ctx[b * MEMD + d + 2], acc.z);
    atomicAdd(&ctx[b * MEMD + d + 3], acc.w);
}

// ---------------------------------------------------------------------------
// Launch.  Inputs (metadata order):
//   0 hidden | 1 memory | 2 mem_pad | 3 coverage | 4 W_h | 5 W_m | 6 W_c | 7 v
// Output: [context (B*MEM) | attn (B*S)] f32
// ---------------------------------------------------------------------------
extern "C" void kernel_launch(void* const* d_in, const int* in_sizes, int n_in,
                              void* d_out, int out_size) {
    const float* hidden   = (const float*)d_in[0];
    const float* memory   = (const float*)d_in[1];
    const unsigned char* mem_pad = (const unsigned char*)d_in[2];
    const float* coverage = (const float*)d_in[3];
    const float* W_h      = (const float*)d_in[4];
    const float* W_m      = (const float*)d_in[5];
    const float* W_c      = (const float*)d_in[6];
    const float* v        = (const float*)d_in[7];

    float* out = (float*)d_out;
    float* out_ctx  = out;
    float* out_attn = out + BB * MEMD;

    cudaFuncSetAttribute(score_mma, cudaFuncAttributeMaxDynamicSharedMemorySize,
                         SMEM_DYN);

    permute_wm16<<<(4 * 16 * 8 * 64 * 4 + 255) / 256, 256>>>(W_m);
    h_kernel<<<BB, 512>>>(hidden, W_h, out_ctx);
    {
        dim3 grid(ATT / BN, BB * SS / BM);
        score_mma<<<grid, 256, SMEM_DYN>>>(memory, coverage, W_c, v);
    }
    softmax_reduce<<<BB, 1024>>>(mem_pad);
    {
        dim3 grid(BB, SS / 64);
        context_kernel<<<grid, 128>>>(memory, mem_pad, out_attn, out_ctx);
    }
}